// round 1
// baseline (speedup 1.0000x reference)
#include <cuda_runtime.h>
#include <math.h>

#define B_      256
#define FERD    2048
#define LMD     256
#define NC      7
#define KNN     8
#define NPAIR   (B_*KNN)     // 2048
#define EPSV    1e-8f

// ---------------- scratch (no allocations allowed) ----------------
struct Scratch {
    float fnorm_fer[B_*FERD];
    float fnorm_lm [B_*LMD];
    float sim_fer  [B_*B_];
    float sim_lm   [B_*B_];
    float feats_fer[B_*FERD];
    float feats_lm [B_*LMD];
    float A_fer [B_*1024];
    float Bm_fer[B_*1024];
    float A_lm  [B_*128];
    float Bm_lm [B_*128];
    float H_fer [NPAIR*1024];
    float H_lm  [NPAIR*128];
    float H2_fer[NPAIR*512];
    float H2_lm [NPAIR*64];
    float score_fer[NPAIR];
    float score_lm [NPAIR];
    int   nbr_fer[NPAIR];
    int   nbr_lm [NPAIR];
};
__device__ Scratch g_s;

// ---------------- row L2-normalize ----------------
__global__ void normalize_rows(const float* __restrict__ x, float* __restrict__ out, int D) {
    int row = blockIdx.x;
    const float* xr = x + (size_t)row * D;
    float s = 0.f;
    for (int k = threadIdx.x; k < D; k += blockDim.x) { float v = xr[k]; s += v*v; }
    __shared__ float red[32];
    int lane = threadIdx.x & 31, wid = threadIdx.x >> 5;
    #pragma unroll
    for (int o = 16; o; o >>= 1) s += __shfl_xor_sync(0xffffffffu, s, o);
    if (lane == 0) red[wid] = s;
    __syncthreads();
    if (wid == 0) {
        s = (lane < (int)(blockDim.x >> 5)) ? red[lane] : 0.f;
        #pragma unroll
        for (int o = 16; o; o >>= 1) s += __shfl_xor_sync(0xffffffffu, s, o);
        if (lane == 0) red[0] = s;
    }
    __syncthreads();
    float inv = 1.0f / sqrtf(red[0]);
    float* orow = out + (size_t)row * D;
    for (int k = threadIdx.x; k < D; k += blockDim.x) orow[k] = xr[k] * inv;
}

// ---------------- generic SGEMM: C[M,N] = act(A(MxK,lda) . B(NxK,ldb)^T + bias) ----
// both operands K-major (dot of rows). 64x64 tile, BK=16, 256 thr, 4x4/thread.
#define BM 64
#define BN 64
#define BK 16
__global__ void __launch_bounds__(256)
gemm_nt(const float* __restrict__ A, int lda,
        const float* __restrict__ B, int ldb,
        const float* __restrict__ bias, int relu,
        float* __restrict__ C, int M, int N, int K)
{
    __shared__ float As[BK][BM + 4];
    __shared__ float Bs[BK][BN + 4];
    int tid = threadIdx.x;
    int tx = tid & 15;   // n
    int ty = tid >> 4;   // m
    int m0 = blockIdx.y * BM;
    int n0 = blockIdx.x * BN;

    float acc[4][4];
    #pragma unroll
    for (int i = 0; i < 4; i++)
        #pragma unroll
        for (int j = 0; j < 4; j++) acc[i][j] = 0.f;

    for (int k0 = 0; k0 < K; k0 += BK) {
        #pragma unroll
        for (int l = 0; l < 4; l++) {
            int e = tid + l * 256;
            int r = e >> 4;
            int kk = e & 15;
            As[kk][r] = A[(size_t)(m0 + r) * lda + k0 + kk];
            Bs[kk][r] = B[(size_t)(n0 + r) * ldb + k0 + kk];
        }
        __syncthreads();
        #pragma unroll
        for (int kk = 0; kk < BK; kk++) {
            float4 av = *(const float4*)(&As[kk][ty * 4]);
            float4 bv = *(const float4*)(&Bs[kk][tx * 4]);
            float a[4] = {av.x, av.y, av.z, av.w};
            float b[4] = {bv.x, bv.y, bv.z, bv.w};
            #pragma unroll
            for (int i = 0; i < 4; i++)
                #pragma unroll
                for (int j = 0; j < 4; j++)
                    acc[i][j] = fmaf(a[i], b[j], acc[i][j]);
        }
        __syncthreads();
    }
    #pragma unroll
    for (int i = 0; i < 4; i++) {
        int m = m0 + ty * 4 + i;
        #pragma unroll
        for (int j = 0; j < 4; j++) {
            int n = n0 + tx * 4 + j;
            float v = acc[i][j];
            if (bias) v += bias[n];
            if (relu) v = fmaxf(v, 0.f);
            C[(size_t)m * N + n] = v;
        }
    }
}

// ---------------- top-8 per row (diag excluded, strict > -> lowest-index ties) ---
__global__ void topk8(const float* __restrict__ sim, int* __restrict__ nbr) {
    int i = threadIdx.x;
    if (i >= B_) return;
    const float* row = sim + (size_t)i * B_;
    int chosen[KNN];
    for (int t = 0; t < KNN; t++) {
        float best = -1e30f; int bi = 0;
        for (int j = 0; j < B_; j++) {
            if (j == i) continue;
            bool used = false;
            for (int u = 0; u < t; u++) if (chosen[u] == j) { used = true; break; }
            if (used) continue;
            float v = row[j];
            if (v > best) { best = v; bi = j; }
        }
        chosen[t] = bi;
        nbr[i * KNN + t] = bi;
    }
}

// ---------------- H[pair] = relu(A[i] + Bm[j] + b1) ----------------
__global__ void build_h(const float* __restrict__ Av, const float* __restrict__ Bv,
                        const float* __restrict__ b1, const int* __restrict__ nbr,
                        float* __restrict__ H, int D) {
    int pair = blockIdx.x;
    int i = pair >> 3;
    int j = nbr[pair];
    const float* ar = Av + (size_t)i * D;
    const float* br = Bv + (size_t)j * D;
    float* hr = H + (size_t)pair * D;
    for (int k = threadIdx.x; k < D; k += blockDim.x)
        hr[k] = fmaxf(ar[k] + br[k] + b1[k], 0.f);
}

// ---------------- score[pair] = sigmoid(H2 . (w3[0]-w3[1]) + (b3[0]-b3[1])) ------
__global__ void score_kernel(const float* __restrict__ H2, const float* __restrict__ w3,
                             const float* __restrict__ b3, float* __restrict__ score, int D) {
    int pair = blockIdx.x * (blockDim.x >> 5) + (threadIdx.x >> 5);
    int lane = threadIdx.x & 31;
    const float* h = H2 + (size_t)pair * D;
    float s = 0.f;
    for (int k = lane; k < D; k += 32) s += h[k] * (w3[k] - w3[D + k]);
    #pragma unroll
    for (int o = 16; o; o >>= 1) s += __shfl_xor_sync(0xffffffffu, s, o);
    if (lane == 0) {
        s += b3[0] - b3[1];
        score[pair] = 1.f / (1.f + expf(-s));
    }
}

// ---------------- softmax(logits), normalize weights, combine with bank ---------
__global__ void combine(const float* __restrict__ logits, const int* __restrict__ idx,
                        const float* __restrict__ bank,
                        const float* __restrict__ sf, const float* __restrict__ sl,
                        const int* __restrict__ nbrf, const int* __restrict__ nbrl,
                        float* __restrict__ out) {
    __shared__ float p[B_][NC];
    __shared__ float colsum[NC];
    int i = threadIdx.x;
    const float* lr = logits + i * NC;
    float m = lr[0];
    #pragma unroll
    for (int c = 1; c < NC; c++) m = fmaxf(m, lr[c]);
    float e[NC]; float ssum = 0.f;
    #pragma unroll
    for (int c = 0; c < NC; c++) { e[c] = expf(lr[c] - m); ssum += e[c]; }
    float invs = 1.f / ssum;
    #pragma unroll
    for (int c = 0; c < NC; c++) p[i][c] = e[c] * invs;
    __syncthreads();
    if (i < NC) {
        float s = 0.f;
        for (int r = 0; r < B_; r++) s += p[r][i];
        colsum[i] = s;
    }
    __syncthreads();
    float Sf = 0.f, Sl = 0.f;
    #pragma unroll
    for (int t = 0; t < KNN; t++) { Sf += sf[i * KNN + t]; Sl += sl[i * KNN + t]; }
    float df = 1.f / (Sf + EPSV), dl = 1.f / (Sl + EPSV);
    float tf[NC], tl[NC];
    #pragma unroll
    for (int c = 0; c < NC; c++) { tf[c] = 0.f; tl[c] = 0.f; }
    #pragma unroll
    for (int t = 0; t < KNN; t++) {
        int jf = nbrf[i * KNN + t]; float wf = sf[i * KNN + t] * df;
        int jl = nbrl[i * KNN + t]; float wl = sl[i * KNN + t] * dl;
        #pragma unroll
        for (int c = 0; c < NC; c++) {
            tf[c] += wf * p[jf][c];
            tl[c] += wl * p[jl][c];
        }
    }
    float ef = (EPSV / (float)B_) * df;
    float el = (EPSV / (float)B_) * dl;
    #pragma unroll
    for (int c = 0; c < NC; c++) {
        float tgt = 0.5f * (tf[c] + ef * colsum[c]) + 0.5f * (tl[c] + el * colsum[c]);
        out[i * NC + c] = bank[(size_t)idx[i] * NC + c] * 0.9f + tgt * 0.1f;
    }
}

// ---------------- launcher ----------------
extern "C" void kernel_launch(void* const* d_in, const int* in_sizes, int n_in,
                              void* d_out, int out_size) {
    const float* fer_x  = (const float*)d_in[0];
    const float* lm_x   = (const float*)d_in[1];
    const float* logits = (const float*)d_in[2];
    const int*   idx    = (const int*)  d_in[3];
    const float* bank   = (const float*)d_in[4];
    const float* f_win  = (const float*)d_in[5];
    const float* f_bin  = (const float*)d_in[6];
    const float* f_w1   = (const float*)d_in[7];
    const float* f_b1   = (const float*)d_in[8];
    const float* f_w2   = (const float*)d_in[9];
    const float* f_b2   = (const float*)d_in[10];
    const float* f_w3   = (const float*)d_in[11];
    const float* f_b3   = (const float*)d_in[12];
    const float* l_win  = (const float*)d_in[13];
    const float* l_bin  = (const float*)d_in[14];
    const float* l_w1   = (const float*)d_in[15];
    const float* l_b1   = (const float*)d_in[16];
    const float* l_w2   = (const float*)d_in[17];
    const float* l_b2   = (const float*)d_in[18];
    const float* l_w3   = (const float*)d_in[19];
    const float* l_b3   = (const float*)d_in[20];
    float* out = (float*)d_out;

    Scratch* s = nullptr;
    cudaGetSymbolAddress((void**)&s, g_s);

    // normalized features + cosine sim + top-8
    normalize_rows<<<B_, 256>>>(fer_x, s->fnorm_fer, FERD);
    normalize_rows<<<B_, 256>>>(lm_x,  s->fnorm_lm,  LMD);
    gemm_nt<<<dim3(B_/BN, B_/BM), 256>>>(s->fnorm_fer, FERD, s->fnorm_fer, FERD,
                                         nullptr, 0, s->sim_fer, B_, B_, FERD);
    gemm_nt<<<dim3(B_/BN, B_/BM), 256>>>(s->fnorm_lm, LMD, s->fnorm_lm, LMD,
                                         nullptr, 0, s->sim_lm, B_, B_, LMD);
    topk8<<<1, B_>>>(s->sim_fer, s->nbr_fer);
    topk8<<<1, B_>>>(s->sim_lm,  s->nbr_lm);

    // feats = x @ w_in^T + b_in
    gemm_nt<<<dim3(FERD/BN, B_/BM), 256>>>(fer_x, FERD, f_win, FERD, f_bin, 0,
                                           s->feats_fer, B_, FERD, FERD);
    gemm_nt<<<dim3(LMD/BN, B_/BM), 256>>>(lm_x, LMD, l_win, LMD, l_bin, 0,
                                          s->feats_lm, B_, LMD, LMD);

    // A = f1 @ w1a^T ; Bm = f2 @ w1b^T
    gemm_nt<<<dim3(1024/BN, B_/BM), 256>>>(s->feats_fer, FERD, f_w1, FERD,
                                           nullptr, 0, s->A_fer, B_, 1024, 1024);
    gemm_nt<<<dim3(1024/BN, B_/BM), 256>>>(s->feats_fer + 1024, FERD, f_w1 + 1024, FERD,
                                           nullptr, 0, s->Bm_fer, B_, 1024, 1024);
    gemm_nt<<<dim3(128/BN, B_/BM), 256>>>(s->feats_lm, LMD, l_w1, LMD,
                                          nullptr, 0, s->A_lm, B_, 128, 128);
    gemm_nt<<<dim3(128/BN, B_/BM), 256>>>(s->feats_lm + 128, LMD, l_w1 + 128, LMD,
                                          nullptr, 0, s->Bm_lm, B_, 128, 128);

    // only 2048 (i, neighbor) pairs matter
    build_h<<<NPAIR, 256>>>(s->A_fer, s->Bm_fer, f_b1, s->nbr_fer, s->H_fer, 1024);
    build_h<<<NPAIR, 128>>>(s->A_lm,  s->Bm_lm,  l_b1, s->nbr_lm,  s->H_lm,  128);

    // H2 = relu(H @ w2^T + b2)
    gemm_nt<<<dim3(512/BN, NPAIR/BM), 256>>>(s->H_fer, 1024, f_w2, 1024, f_b2, 1,
                                             s->H2_fer, NPAIR, 512, 1024);
    gemm_nt<<<dim3(64/BN, NPAIR/BM), 256>>>(s->H_lm, 128, l_w2, 128, l_b2, 1,
                                            s->H2_lm, NPAIR, 64, 128);

    // softmax over 2 logits == sigmoid of the logit difference
    score_kernel<<<NPAIR/8, 256>>>(s->H2_fer, f_w3, f_b3, s->score_fer, 512);
    score_kernel<<<NPAIR/8, 256>>>(s->H2_lm,  l_w3, l_b3, s->score_lm,  64);

    combine<<<1, B_>>>(logits, idx, bank, s->score_fer, s->score_lm,
                       s->nbr_fer, s->nbr_lm, out);
}

// round 3
// speedup vs baseline: 3.6908x; 3.6908x over previous
#include <cuda_runtime.h>
#include <cuda_bf16.h>
#include <cstdint>
#include <math.h>

#define B_      256
#define FERD    2048
#define LMD     256
#define NC      7
#define KNN     8
#define NPAIR   (B_*KNN)     // 2048
#define EPSV    1e-8f

__device__ __forceinline__ uint32_t smem_to_u32(const void* p) {
    uint32_t a;
    asm("{ .reg .u64 t; cvta.to.shared.u64 t, %1; cvt.u32.u64 %0, t; }" : "=r"(a) : "l"(p));
    return a;
}

// ====================================================================
// scratch (no allocations allowed)
// ====================================================================
struct __align__(16) Scratch {
    // bf16 operands
    __nv_bfloat16 w_in_b[FERD*FERD];
    __nv_bfloat16 w1_b  [1024*FERD];
    __nv_bfloat16 w2_b  [512*1024];
    __nv_bfloat16 xb_fer[B_*FERD];
    __nv_bfloat16 l_win_b[LMD*LMD];
    __nv_bfloat16 l_w1_b [128*LMD];
    __nv_bfloat16 xb_lm  [B_*LMD];
    __nv_bfloat16 feats_fer_b[B_*FERD];
    __nv_bfloat16 feats_lm_b [B_*LMD];
    __nv_bfloat16 H_fer_b[NPAIR*1024];
    // fp32
    float fnorm_fer[B_*FERD];
    float fnorm_lm [B_*LMD];
    float sim_fer[B_*B_], sim_lm[B_*B_];
    float A_fer[B_*1024], Bm_fer[B_*1024];
    float A_lm [B_*128],  Bm_lm [B_*128];
    float H_lm [NPAIR*128];
    float H2_fer[NPAIR*512], H2_lm[NPAIR*64];
    float score_fer[NPAIR], score_lm[NPAIR];
    int   nbr_fer[NPAIR], nbr_lm[NPAIR];
};
__device__ Scratch g_s;

// ====================================================================
// fp32 -> bf16 conversion of all tensor operands, one launch
// ====================================================================
#define CN1 (FERD*FERD)
#define CN2 (1024*FERD)
#define CN3 (512*1024)
#define CN4 (B_*FERD)
#define CN5 (LMD*LMD)
#define CN6 (128*LMD)
#define CN7 (B_*LMD)
#define CTOT (CN1+CN2+CN3+CN4+CN5+CN6+CN7)
__global__ void convert_all(const float* __restrict__ fw_in, const float* __restrict__ fw1,
                            const float* __restrict__ fw2,  const float* __restrict__ fx,
                            const float* __restrict__ lwin, const float* __restrict__ lw1,
                            const float* __restrict__ lx,   Scratch* s) {
    int total4 = CTOT / 4;
    for (int i = blockIdx.x * blockDim.x + threadIdx.x; i < total4;
         i += gridDim.x * blockDim.x) {
        int j = i * 4;
        const float* src; __nv_bfloat16* dst; int off;
        if      (j < CN1)                         { src=fw_in; dst=s->w_in_b;  off=j; }
        else if (j < CN1+CN2)                     { src=fw1;   dst=s->w1_b;    off=j-CN1; }
        else if (j < CN1+CN2+CN3)                 { src=fw2;   dst=s->w2_b;    off=j-CN1-CN2; }
        else if (j < CN1+CN2+CN3+CN4)             { src=fx;    dst=s->xb_fer;  off=j-CN1-CN2-CN3; }
        else if (j < CN1+CN2+CN3+CN4+CN5)         { src=lwin;  dst=s->l_win_b; off=j-CN1-CN2-CN3-CN4; }
        else if (j < CN1+CN2+CN3+CN4+CN5+CN6)     { src=lw1;   dst=s->l_w1_b;  off=j-CN1-CN2-CN3-CN4-CN5; }
        else                                      { src=lx;    dst=s->xb_lm;   off=j-CN1-CN2-CN3-CN4-CN5-CN6; }
        float4 v = *(const float4*)(src + off);
        *(__nv_bfloat162*)(dst + off)     = __floats2bfloat162_rn(v.x, v.y);
        *(__nv_bfloat162*)(dst + off + 2) = __floats2bfloat162_rn(v.z, v.w);
    }
}

// ====================================================================
// bf16 HMMA GEMM: C[M,N] = act(A(MxK,lda) . B(NxK,ldb)^T + bias)
// block tile 128x128, BK=64, 8 warps (2x4), warp tile 64x32,
// mma.sync m16n8k16, cp.async double buffer. M,N mult of 128, K mult of 64.
// ====================================================================
#define MM_LDS   72                     // padded row stride (elements)
#define MM_ATILE (128*MM_LDS*2)         // 18432 bytes
#define MM_BUF   (2*MM_ATILE)           // A + B
#define MM_SMEM  (2*MM_BUF)             // double buffer = 73728

__global__ void __launch_bounds__(256)
gemm_mma(const __nv_bfloat16* __restrict__ A, int lda,
         const __nv_bfloat16* __restrict__ B, int ldb,
         const float* __restrict__ bias, int relu,
         float* __restrict__ Cf, __nv_bfloat16* __restrict__ Cb,
         int N, int K)
{
    extern __shared__ char smem[];
    uint32_t sb = smem_to_u32(smem);
    int tid = threadIdx.x;
    int lane = tid & 31, warp = tid >> 5;
    int wm = warp >> 2, wn = warp & 3;       // 2 x 4 warps
    int m0 = blockIdx.y * 128, n0 = blockIdx.x * 128;

    float acc[4][4][4];
    #pragma unroll
    for (int i = 0; i < 4; i++)
        #pragma unroll
        for (int j = 0; j < 4; j++)
            #pragma unroll
            for (int q = 0; q < 4; q++) acc[i][j][q] = 0.f;

    int nk = K >> 6;

    // -------- async tile loader --------
    auto issue = [&](int kt) {
        int s = kt & 1;
        uint32_t base = sb + s * MM_BUF;
        int k0 = kt * 64;
        #pragma unroll
        for (int u = 0; u < 4; u++) {
            int cc = tid * 4 + u;            // 0..1023
            int row = cc >> 3;
            int col = (cc & 7) * 8;
            uint32_t da = base + (uint32_t)(row * MM_LDS + col) * 2;
            const __nv_bfloat16* ga = A + (size_t)(m0 + row) * lda + k0 + col;
            asm volatile("cp.async.cg.shared.global [%0], [%1], 16;"
                         :: "r"(da), "l"(ga));
            const __nv_bfloat16* gb = B + (size_t)(n0 + row) * ldb + k0 + col;
            asm volatile("cp.async.cg.shared.global [%0], [%1], 16;"
                         :: "r"(da + MM_ATILE), "l"(gb));
        }
        asm volatile("cp.async.commit_group;" ::: "memory");
    };

    issue(0);
    for (int kt = 0; kt < nk; kt++) {
        if (kt + 1 < nk) {
            issue(kt + 1);
            asm volatile("cp.async.wait_group 1;" ::: "memory");
        } else {
            asm volatile("cp.async.wait_group 0;" ::: "memory");
        }
        __syncthreads();

        uint32_t aBase = sb + (kt & 1) * MM_BUF;
        uint32_t bBase = aBase + MM_ATILE;
        #pragma unroll
        for (int ks = 0; ks < 4; ks++) {
            int k = ks * 16;
            uint32_t af[4][4];
            #pragma unroll
            for (int im = 0; im < 4; im++) {
                int row = wm * 64 + im * 16 + (lane & 15);
                int kg = (lane >> 4) * 8;
                uint32_t addr = aBase + (uint32_t)(row * MM_LDS + k + kg) * 2;
                asm volatile("ldmatrix.sync.aligned.m8n8.x4.shared.b16 {%0,%1,%2,%3}, [%4];"
                             : "=r"(af[im][0]), "=r"(af[im][1]),
                               "=r"(af[im][2]), "=r"(af[im][3])
                             : "r"(addr));
            }
            uint32_t bf[4][2];
            #pragma unroll
            for (int in = 0; in < 4; in++) {
                int l = lane & 15;
                int n = wn * 32 + in * 8 + (l & 7);
                int kg = (l >> 3) * 8;
                uint32_t addr = bBase + (uint32_t)(n * MM_LDS + k + kg) * 2;
                asm volatile("ldmatrix.sync.aligned.m8n8.x2.shared.b16 {%0,%1}, [%2];"
                             : "=r"(bf[in][0]), "=r"(bf[in][1])
                             : "r"(addr));
            }
            #pragma unroll
            for (int im = 0; im < 4; im++)
                #pragma unroll
                for (int in = 0; in < 4; in++) {
                    asm volatile(
                        "mma.sync.aligned.m16n8k16.row.col.f32.bf16.bf16.f32 "
                        "{%0,%1,%2,%3}, {%4,%5,%6,%7}, {%8,%9}, {%0,%1,%2,%3};"
                        : "+f"(acc[im][in][0]), "+f"(acc[im][in][1]),
                          "+f"(acc[im][in][2]), "+f"(acc[im][in][3])
                        : "r"(af[im][0]), "r"(af[im][1]), "r"(af[im][2]), "r"(af[im][3]),
                          "r"(bf[in][0]), "r"(bf[in][1]));
                }
        }
        __syncthreads();
    }

    // -------- epilogue --------
    #pragma unroll
    for (int im = 0; im < 4; im++) {
        int m = m0 + wm * 64 + im * 16 + (lane >> 2);
        #pragma unroll
        for (int in = 0; in < 4; in++) {
            int n = n0 + wn * 32 + in * 8 + (lane & 3) * 2;
            float b0 = bias ? bias[n]     : 0.f;
            float b1 = bias ? bias[n + 1] : 0.f;
            float v00 = acc[im][in][0] + b0, v01 = acc[im][in][1] + b1;
            float v10 = acc[im][in][2] + b0, v11 = acc[im][in][3] + b1;
            if (relu) {
                v00 = fmaxf(v00, 0.f); v01 = fmaxf(v01, 0.f);
                v10 = fmaxf(v10, 0.f); v11 = fmaxf(v11, 0.f);
            }
            if (Cf) {
                *(float2*)(Cf + (size_t)m * N + n)       = make_float2(v00, v01);
                *(float2*)(Cf + (size_t)(m + 8) * N + n) = make_float2(v10, v11);
            } else {
                *(__nv_bfloat162*)(Cb + (size_t)m * N + n) =
                    __floats2bfloat162_rn(v00, v01);
                *(__nv_bfloat162*)(Cb + (size_t)(m + 8) * N + n) =
                    __floats2bfloat162_rn(v10, v11);
            }
        }
    }
}

// ====================================================================
// row L2-normalize (fp32, for the discrete top-k path)
// ====================================================================
__global__ void normalize_rows(const float* __restrict__ x, float* __restrict__ out, int D) {
    int row = blockIdx.x;
    const float* xr = x + (size_t)row * D;
    float s = 0.f;
    for (int k = threadIdx.x; k < D; k += blockDim.x) { float v = xr[k]; s += v * v; }
    __shared__ float red[32];
    int lane = threadIdx.x & 31, wid = threadIdx.x >> 5;
    #pragma unroll
    for (int o = 16; o; o >>= 1) s += __shfl_xor_sync(0xffffffffu, s, o);
    if (lane == 0) red[wid] = s;
    __syncthreads();
    if (wid == 0) {
        s = (lane < (int)(blockDim.x >> 5)) ? red[lane] : 0.f;
        #pragma unroll
        for (int o = 16; o; o >>= 1) s += __shfl_xor_sync(0xffffffffu, s, o);
        if (lane == 0) red[0] = s;
    }
    __syncthreads();
    float inv = 1.0f / sqrtf(red[0]);
    float* orow = out + (size_t)row * D;
    for (int k = threadIdx.x; k < D; k += blockDim.x) orow[k] = xr[k] * inv;
}

// ====================================================================
// fp32 SIMT GEMM (sim matrices + tiny LM H2 GEMM)
// ====================================================================
#define BM 64
#define BN 64
#define BK 16
__global__ void __launch_bounds__(256)
gemm_nt(const float* __restrict__ A, int lda,
        const float* __restrict__ B, int ldb,
        const float* __restrict__ bias, int relu,
        float* __restrict__ C, int M, int N, int K)
{
    __shared__ float As[BK][BM + 4];
    __shared__ float Bs[BK][BN + 4];
    int tid = threadIdx.x;
    int tx = tid & 15, ty = tid >> 4;
    int m0 = blockIdx.y * BM, n0 = blockIdx.x * BN;
    float acc[4][4];
    #pragma unroll
    for (int i = 0; i < 4; i++)
        #pragma unroll
        for (int j = 0; j < 4; j++) acc[i][j] = 0.f;
    for (int k0 = 0; k0 < K; k0 += BK) {
        #pragma unroll
        for (int l = 0; l < 4; l++) {
            int e = tid + l * 256;
            int r = e >> 4, kk = e & 15;
            As[kk][r] = A[(size_t)(m0 + r) * lda + k0 + kk];
            Bs[kk][r] = B[(size_t)(n0 + r) * ldb + k0 + kk];
        }
        __syncthreads();
        #pragma unroll
        for (int kk = 0; kk < BK; kk++) {
            float4 av = *(const float4*)(&As[kk][ty * 4]);
            float4 bv = *(const float4*)(&Bs[kk][tx * 4]);
            float a[4] = {av.x, av.y, av.z, av.w};
            float b[4] = {bv.x, bv.y, bv.z, bv.w};
            #pragma unroll
            for (int i = 0; i < 4; i++)
                #pragma unroll
                for (int j = 0; j < 4; j++)
                    acc[i][j] = fmaf(a[i], b[j], acc[i][j]);
        }
        __syncthreads();
    }
    #pragma unroll
    for (int i = 0; i < 4; i++) {
        int m = m0 + ty * 4 + i;
        #pragma unroll
        for (int j = 0; j < 4; j++) {
            int n = n0 + tx * 4 + j;
            float v = acc[i][j];
            if (bias) v += bias[n];
            if (relu) v = fmaxf(v, 0.f);
            C[(size_t)m * N + n] = v;
        }
    }
}

// ====================================================================
// top-8 per row, warp per row; strict >, lowest index wins ties
// ====================================================================
__global__ void topk8_warp(const float* __restrict__ sim, int* __restrict__ nbr) {
    int warp = blockIdx.x * (blockDim.x >> 5) + (threadIdx.x >> 5);
    int lane = threadIdx.x & 31;
    if (warp >= B_) return;
    const float* row = sim + (size_t)warp * B_;
    float v[8];
    #pragma unroll
    for (int t = 0; t < 8; t++) {
        int j = lane + t * 32;
        v[t] = (j == warp) ? -1e30f : row[j];
    }
    for (int t = 0; t < KNN; t++) {
        float bv = -1e30f; int bi = 0x7fffffff;
        #pragma unroll
        for (int q = 0; q < 8; q++) {
            int j = lane + q * 32;
            if (v[q] > bv || (v[q] == bv && j < bi)) { bv = v[q]; bi = j; }
        }
        #pragma unroll
        for (int o = 16; o; o >>= 1) {
            float ov = __shfl_xor_sync(0xffffffffu, bv, o);
            int   oi = __shfl_xor_sync(0xffffffffu, bi, o);
            if (ov > bv || (ov == bv && oi < bi)) { bv = ov; bi = oi; }
        }
        if (lane == 0) nbr[warp * KNN + t] = bi;
        if (lane == (bi & 31)) v[bi >> 5] = -1e30f;
    }
}

// ====================================================================
// H[pair] = relu(A[i] + Bm[j] + b1)  — bf16 and fp32 output variants
// ====================================================================
__global__ void build_h_bf16(const float* __restrict__ Av, const float* __restrict__ Bv,
                             const float* __restrict__ b1, const int* __restrict__ nbr,
                             __nv_bfloat16* __restrict__ H, int D) {
    int pair = blockIdx.x;
    int i = pair >> 3;
    int j = nbr[pair];
    const float* ar = Av + (size_t)i * D;
    const float* br = Bv + (size_t)j * D;
    __nv_bfloat16* hr = H + (size_t)pair * D;
    for (int k = threadIdx.x; k < D; k += blockDim.x)
        hr[k] = __float2bfloat16(fmaxf(ar[k] + br[k] + b1[k], 0.f));
}
__global__ void build_h_f32(const float* __restrict__ Av, const float* __restrict__ Bv,
                            const float* __restrict__ b1, const int* __restrict__ nbr,
                            float* __restrict__ H, int D) {
    int pair = blockIdx.x;
    int i = pair >> 3;
    int j = nbr[pair];
    const float* ar = Av + (size_t)i * D;
    const float* br = Bv + (size_t)j * D;
    float* hr = H + (size_t)pair * D;
    for (int k = threadIdx.x; k < D; k += blockDim.x)
        hr[k] = fmaxf(ar[k] + br[k] + b1[k], 0.f);
}

// ====================================================================
// score[pair] = sigmoid(H2 . (w3[0]-w3[1]) + (b3[0]-b3[1]))
// ====================================================================
__global__ void score_kernel(const float* __restrict__ H2, const float* __restrict__ w3,
                             const float* __restrict__ b3, float* __restrict__ score, int D) {
    int pair = blockIdx.x * (blockDim.x >> 5) + (threadIdx.x >> 5);
    int lane = threadIdx.x & 31;
    const float* h = H2 + (size_t)pair * D;
    float s = 0.f;
    for (int k = lane; k < D; k += 32) s += h[k] * (w3[k] - w3[D + k]);
    #pragma unroll
    for (int o = 16; o; o >>= 1) s += __shfl_xor_sync(0xffffffffu, s, o);
    if (lane == 0) {
        s += b3[0] - b3[1];
        score[pair] = 1.f / (1.f + expf(-s));
    }
}

// ====================================================================
// softmax(logits), normalize weights, combine with bank
// ====================================================================
__global__ void combine(const float* __restrict__ logits, const int* __restrict__ idx,
                        const float* __restrict__ bank,
                        const float* __restrict__ sf, const float* __restrict__ sl,
                        const int* __restrict__ nbrf, const int* __restrict__ nbrl,
                        float* __restrict__ out) {
    __shared__ float p[B_][NC];
    __shared__ float colsum[NC];
    int i = threadIdx.x;
    const float* lr = logits + i * NC;
    float m = lr[0];
    #pragma unroll
    for (int c = 1; c < NC; c++) m = fmaxf(m, lr[c]);
    float e[NC]; float ssum = 0.f;
    #pragma unroll
    for (int c = 0; c < NC; c++) { e[c] = expf(lr[c] - m); ssum += e[c]; }
    float invs = 1.f / ssum;
    #pragma unroll
    for (int c = 0; c < NC; c++) p[i][c] = e[c] * invs;
    __syncthreads();
    if (i < NC) {
        float s = 0.f;
        for (int r = 0; r < B_; r++) s += p[r][i];
        colsum[i] = s;
    }
    __syncthreads();
    float Sf = 0.f, Sl = 0.f;
    #pragma unroll
    for (int t = 0; t < KNN; t++) { Sf += sf[i * KNN + t]; Sl += sl[i * KNN + t]; }
    float df = 1.f / (Sf + EPSV), dl = 1.f / (Sl + EPSV);
    float tf[NC], tl[NC];
    #pragma unroll
    for (int c = 0; c < NC; c++) { tf[c] = 0.f; tl[c] = 0.f; }
    #pragma unroll
    for (int t = 0; t < KNN; t++) {
        int jf = nbrf[i * KNN + t]; float wf = sf[i * KNN + t] * df;
        int jl = nbrl[i * KNN + t]; float wl = sl[i * KNN + t] * dl;
        #pragma unroll
        for (int c = 0; c < NC; c++) {
            tf[c] += wf * p[jf][c];
            tl[c] += wl * p[jl][c];
        }
    }
    float ef = (EPSV / (float)B_) * df;
    float el = (EPSV / (float)B_) * dl;
    #pragma unroll
    for (int c = 0; c < NC; c++) {
        float tgt = 0.5f * (tf[c] + ef * colsum[c]) + 0.5f * (tl[c] + el * colsum[c]);
        out[i * NC + c] = bank[(size_t)idx[i] * NC + c] * 0.9f + tgt * 0.1f;
    }
}

// ====================================================================
// launcher
// ====================================================================
extern "C" void kernel_launch(void* const* d_in, const int* in_sizes, int n_in,
                              void* d_out, int out_size) {
    const float* fer_x  = (const float*)d_in[0];
    const float* lm_x   = (const float*)d_in[1];
    const float* logits = (const float*)d_in[2];
    const int*   idx    = (const int*)  d_in[3];
    const float* bank   = (const float*)d_in[4];
    const float* f_win  = (const float*)d_in[5];
    const float* f_bin  = (const float*)d_in[6];
    const float* f_w1   = (const float*)d_in[7];
    const float* f_b1   = (const float*)d_in[8];
    const float* f_w2   = (const float*)d_in[9];
    const float* f_b2   = (const float*)d_in[10];
    const float* f_w3   = (const float*)d_in[11];
    const float* f_b3   = (const float*)d_in[12];
    const float* l_win  = (const float*)d_in[13];
    const float* l_bin  = (const float*)d_in[14];
    const float* l_w1   = (const float*)d_in[15];
    const float* l_b1   = (const float*)d_in[16];
    const float* l_w2   = (const float*)d_in[17];
    const float* l_b2   = (const float*)d_in[18];
    const float* l_w3   = (const float*)d_in[19];
    const float* l_b3   = (const float*)d_in[20];
    float* out = (float*)d_out;

    Scratch* s = nullptr;
    cudaGetSymbolAddress((void**)&s, g_s);
    cudaFuncSetAttribute(gemm_mma, cudaFuncAttributeMaxDynamicSharedMemorySize, MM_SMEM);

    // bf16 conversions (one launch)
    convert_all<<<1024, 256>>>(f_win, f_w1, f_w2, fer_x, l_win, l_w1, lm_x, s);

    // --- discrete path: fp32 cosine sim + top-8 ---
    normalize_rows<<<B_, 256>>>(fer_x, s->fnorm_fer, FERD);
    normalize_rows<<<B_, 256>>>(lm_x,  s->fnorm_lm,  LMD);
    gemm_nt<<<dim3(B_/BN, B_/BM), 256>>>(s->fnorm_fer, FERD, s->fnorm_fer, FERD,
                                         nullptr, 0, s->sim_fer, B_, B_, FERD);
    gemm_nt<<<dim3(B_/BN, B_/BM), 256>>>(s->fnorm_lm, LMD, s->fnorm_lm, LMD,
                                         nullptr, 0, s->sim_lm, B_, B_, LMD);
    topk8_warp<<<32, 256>>>(s->sim_fer, s->nbr_fer);
    topk8_warp<<<32, 256>>>(s->sim_lm,  s->nbr_lm);

    // --- FER branch (HMMA tensor cores) ---
    gemm_mma<<<dim3(FERD/128, B_/128), 256, MM_SMEM>>>(
        s->xb_fer, FERD, s->w_in_b, FERD, f_bin, 0, nullptr, s->feats_fer_b, FERD, FERD);
    gemm_mma<<<dim3(1024/128, B_/128), 256, MM_SMEM>>>(
        s->feats_fer_b, FERD, s->w1_b, FERD, nullptr, 0, s->A_fer, nullptr, 1024, 1024);
    gemm_mma<<<dim3(1024/128, B_/128), 256, MM_SMEM>>>(
        s->feats_fer_b + 1024, FERD, s->w1_b + 1024, FERD, nullptr, 0, s->Bm_fer, nullptr, 1024, 1024);
    build_h_bf16<<<NPAIR, 256>>>(s->A_fer, s->Bm_fer, f_b1, s->nbr_fer, s->H_fer_b, 1024);
    gemm_mma<<<dim3(512/128, NPAIR/128), 256, MM_SMEM>>>(
        s->H_fer_b, 1024, s->w2_b, 1024, f_b2, 1, s->H2_fer, nullptr, 512, 1024);
    score_kernel<<<NPAIR/8, 256>>>(s->H2_fer, f_w3, f_b3, s->score_fer, 512);

    // --- LM branch ---
    gemm_mma<<<dim3(LMD/128, B_/128), 256, MM_SMEM>>>(
        s->xb_lm, LMD, s->l_win_b, LMD, l_bin, 0, nullptr, s->feats_lm_b, LMD, LMD);
    gemm_mma<<<dim3(1, B_/128), 256, MM_SMEM>>>(
        s->feats_lm_b, LMD, s->l_w1_b, LMD, nullptr, 0, s->A_lm, nullptr, 128, 128);
    gemm_mma<<<dim3(1, B_/128), 256, MM_SMEM>>>(
        s->feats_lm_b + 128, LMD, s->l_w1_b + 128, LMD, nullptr, 0, s->Bm_lm, nullptr, 128, 128);
    build_h_f32<<<NPAIR, 128>>>(s->A_lm, s->Bm_lm, l_b1, s->nbr_lm, s->H_lm, 128);
    gemm_nt<<<dim3(1, NPAIR/BM), 256>>>(s->H_lm, 128, l_w2, 128, l_b2, 1,
                                        s->H2_lm, NPAIR, 64, 128);
    score_kernel<<<NPAIR/8, 256>>>(s->H2_lm, l_w3, l_b3, s->score_lm, 64);

    // --- final combine ---
    combine<<<1, B_>>>(logits, idx, bank, s->score_fer, s->score_lm,
                       s->nbr_fer, s->nbr_lm, out);
}